// round 15
// baseline (speedup 1.0000x reference)
#include <cuda_runtime.h>
#include <cuda_bf16.h>
#include <cstdint>

#define B_   64
#define T_   4096
#define DIM_ 256
#define NF_  32
#define KS_  31
#define PAD_ 15
#define NEG_ (-1e30f)
#define BT_  (B_ * T_)
#define NSPLIT 16
#define CE    2.885390081777926815f   // 2*log2(e)

// ---------------- scratch (device globals; no allocations) ----------------
__device__ float g_q[B_ * DIM_];                     // 64 KB
__device__ float g_S[BT_];                           // raw masked scores
__device__ float g_partial[NSPLIT * B_ * DIM_];      // context partials
__device__ float g_align_scratch[BT_];
__device__ float g_att_scratch[B_ * DIM_];
__device__ int   g_det[2];

// ---------------- K0: mask dtype detection ----------------
__global__ void k_reset() { g_det[0] = 0; g_det[1] = 0; }

// sample first 65536 words (256KB == min possible mask buffer size)
__global__ void k_detect(const unsigned int* __restrict__ mw) {
    int i = (blockIdx.x * 256 + threadIdx.x) * 4;
#pragma unroll
    for (int j = 0; j < 4; ++j) {
        unsigned v = mw[i + j];
        if (v == 0x3f800000u)      atomicOr(&g_det[1], 1);   // float 1.0
        else if (v > 1u)           atomicOr(&g_det[0], 1);   // packed bytes
    }
}

__device__ __forceinline__ bool mask_at(const void* m, int idx, int isf, int isu8) {
    if (isf)  return ((const float*)m)[idx] != 0.0f;
    if (isu8) return ((const unsigned char*)m)[idx] != 0;
    return ((const int*)m)[idx] != 0;
}

// ---------------- K1: q = query @ Wq^T  (4-way interleaved, 128 blocks) ---
__global__ void __launch_bounds__(256) k_qproj(const float* __restrict__ query,
                                               const float* __restrict__ Wq) {
    __shared__ float qs[DIM_];
    const int b = blockIdx.y, half = blockIdx.x;
    const int tid = threadIdx.x, w = tid >> 5, lane = tid & 31;
    qs[tid] = query[b * DIM_ + tid];
    __syncthreads();
    const int dbase = half * 128 + w * 16;
#pragma unroll
    for (int it = 0; it < 4; ++it) {
        const int d0 = dbase + it * 4;
        float a0 = 0.f, a1 = 0.f, a2 = 0.f, a3 = 0.f;
        const float* r0 = Wq + (size_t)(d0 + 0) * DIM_;
        const float* r1 = Wq + (size_t)(d0 + 1) * DIM_;
        const float* r2 = Wq + (size_t)(d0 + 2) * DIM_;
        const float* r3 = Wq + (size_t)(d0 + 3) * DIM_;
#pragma unroll
        for (int e = 0; e < 8; ++e) {
            const int c = lane + 32 * e;
            const float q = qs[c];
            a0 = fmaf(r0[c], q, a0);
            a1 = fmaf(r1[c], q, a1);
            a2 = fmaf(r2[c], q, a2);
            a3 = fmaf(r3[c], q, a3);
        }
#pragma unroll
        for (int o = 16; o > 0; o >>= 1) {
            a0 += __shfl_xor_sync(0xffffffffu, a0, o);
            a1 += __shfl_xor_sync(0xffffffffu, a1, o);
            a2 += __shfl_xor_sync(0xffffffffu, a2, o);
            a3 += __shfl_xor_sync(0xffffffffu, a3, o);
        }
        if (lane == 0)
            *(float4*)&g_q[b * DIM_ + d0] = make_float4(a0, a1, a2, a3);
    }
}

// ---------------- K3: fused conv + score kernel ----------------
#define FP 40   // bf16 smem pitch: conflict-free v1/v2 fragment loads

__global__ void __launch_bounds__(256)
k_score(const float* __restrict__ keys, const float* __restrict__ Wloc,
        const float* __restrict__ vw, const float* __restrict__ vb,
        const void* __restrict__ mask,
        const float* __restrict__ pa, const float* __restrict__ cw) {
    __shared__ __align__(16) __nv_bfloat16 F_sh[128 * FP];    // 10.0 KB
    __shared__ __align__(16) __nv_bfloat16 W_sh[DIM_ * FP];   // 20.0 KB
    __shared__ float qC_sh[DIM_], vm_sh[DIM_];                 // q*CE, -2*v
    __shared__ float pa_sh[160];
    __shared__ float cw_sh[NF_ * KS_];
    __shared__ float sh_V;                                     // sum of v_w

    const int b = blockIdx.y, t0 = blockIdx.x * 128;
    const int tid = threadIdx.x, w = tid >> 5, lane = tid & 31;
    const int g = lane >> 2, tg = lane & 3;

    // ---- stage everything (one block sync total) ----
    for (int idx = tid; idx < DIM_ * NF_; idx += 256)
        W_sh[(idx >> 5) * FP + (idx & 31)] = __float2bfloat16(Wloc[idx]);
    qC_sh[tid] = g_q[b * DIM_ + tid] * CE;
    const float vme = vw[tid];
    vm_sh[tid] = -2.0f * vme;
    for (int i = tid; i < 160; i += 256) {
        int t = t0 + i - PAD_;
        pa_sh[i] = (t >= 0 && t < T_) ? pa[b * T_ + t] : 0.0f;
    }
    for (int i = tid; i < NF_ * KS_; i += 256) cw_sh[i] = cw[i];
    const float vb0 = vb[0];
    __syncthreads();

    // ---- V = sum(v_w) (warp 0), overlapped with conv below ----
    if (w == 0) {
        float s = 0.0f;
#pragma unroll
        for (int e = 0; e < 8; ++e) s += vm_sh[lane + 32 * e];
#pragma unroll
        for (int o = 16; o > 0; o >>= 1) s += __shfl_xor_sync(0xffffffffu, s, o);
        if (lane == 0) sh_V = -0.5f * s;
    }

    // ---- conv for this warp's own 16 t-rows (lane = filter) ----
    {
        float cr[KS_];
#pragma unroll
        for (int k = 0; k < KS_; ++k) cr[k] = cw_sh[lane * KS_ + k];  // stride-31: conflict-free
        float wv[KS_];
#pragma unroll
        for (int k = 0; k < KS_; ++k) wv[k] = pa_sh[w * 16 + k];      // broadcast
        uint32_t* Frow = (uint32_t*)(F_sh + (w * 16) * FP);
#pragma unroll
        for (int i = 0; i < 16; ++i) {
            float a = 0.0f;
#pragma unroll
            for (int k = 0; k < KS_; ++k) a = fmaf(wv[k], cr[k], a);
            unsigned short us = __bfloat16_as_ushort(__float2bfloat16(a));
            unsigned nxt = __shfl_down_sync(0xffffffffu, (unsigned)us, 1);
            if (!(lane & 1))  // 16 lanes, stride-2 words: conflict-free STS.32
                Frow[i * (FP / 2) + (lane >> 1)] = (unsigned)us | (nxt << 16);
#pragma unroll
            for (int k = 0; k < KS_ - 1; ++k) wv[k] = wv[k + 1];
            wv[KS_ - 1] = pa_sh[w * 16 + i + KS_];                    // max 158 < 160
        }
    }
    __syncwarp();   // F_sh rows produced and consumed by the same warp

    // ---- A fragments (m16k16, 2 k-steps) for this warp's 16 t-rows ----
    const __nv_bfloat16* Fb = F_sh + (w * 16) * FP;
    uint32_t a[2][4];
#pragma unroll
    for (int ks = 0; ks < 2; ++ks) {
        const int f0 = ks * 16 + 2 * tg;
        a[ks][0] = *(const uint32_t*)(Fb + g * FP + f0);
        a[ks][1] = *(const uint32_t*)(Fb + (g + 8) * FP + f0);
        a[ks][2] = *(const uint32_t*)(Fb + g * FP + f0 + 8);
        a[ks][3] = *(const uint32_t*)(Fb + (g + 8) * FP + f0 + 8);
    }

    const size_t row0 = (size_t)(b * T_ + t0 + w * 16 + g) * DIM_;
    const size_t row8 = row0 + 8 * DIM_;
    float sc0 = 0.0f, sc1 = 0.0f;

#pragma unroll 2
    for (int nt = 0; nt < 32; ++nt) {
        const int n0 = nt * 8;
        const int d  = n0 + 2 * tg;
        const __nv_bfloat16* Wb = W_sh + (n0 + g) * FP + 2 * tg;
        const uint32_t b00 = *(const uint32_t*)(Wb);
        const uint32_t b01 = *(const uint32_t*)(Wb + 8);
        const uint32_t b10 = *(const uint32_t*)(Wb + 16);
        const uint32_t b11 = *(const uint32_t*)(Wb + 24);
        // prefetch keys + per-d constants while MMA runs
        const float2 k0 = *(const float2*)(keys + row0 + d);
        const float2 k1 = *(const float2*)(keys + row8 + d);
        const float2 q2 = *(const float2*)&qC_sh[d];
        const float2 v2 = *(const float2*)&vm_sh[d];

        float c0 = 0.f, c1 = 0.f, c2 = 0.f, c3 = 0.f;
        asm volatile(
            "mma.sync.aligned.m16n8k16.row.col.f32.bf16.bf16.f32 "
            "{%0,%1,%2,%3}, {%4,%5,%6,%7}, {%8,%9}, {%0,%1,%2,%3};"
            : "+f"(c0), "+f"(c1), "+f"(c2), "+f"(c3)
            : "r"(a[0][0]), "r"(a[0][1]), "r"(a[0][2]), "r"(a[0][3]),
              "r"(b00), "r"(b01));
        asm volatile(
            "mma.sync.aligned.m16n8k16.row.col.f32.bf16.bf16.f32 "
            "{%0,%1,%2,%3}, {%4,%5,%6,%7}, {%8,%9}, {%0,%1,%2,%3};"
            : "+f"(c0), "+f"(c1), "+f"(c2), "+f"(c3)
            : "r"(a[1][0]), "r"(a[1][1]), "r"(a[1][2]), "r"(a[1][3]),
              "r"(b10), "r"(b11));

        // v*tanh(x) = v - 2v*rcp(ex2(x*CE)+1);  vm = -2v, V added at end
        const float kC0x = fmaf(k0.x, CE, q2.x);
        const float kC0y = fmaf(k0.y, CE, q2.y);
        const float kC1x = fmaf(k1.x, CE, q2.x);
        const float kC1y = fmaf(k1.y, CE, q2.y);
        float e0, e1, e2, e3, r0, r1, r2, r3;
        asm("ex2.approx.f32 %0, %1;" : "=f"(e0) : "f"(fmaf(c0, CE, kC0x)));
        asm("ex2.approx.f32 %0, %1;" : "=f"(e1) : "f"(fmaf(c1, CE, kC0y)));
        asm("ex2.approx.f32 %0, %1;" : "=f"(e2) : "f"(fmaf(c2, CE, kC1x)));
        asm("ex2.approx.f32 %0, %1;" : "=f"(e3) : "f"(fmaf(c3, CE, kC1y)));
        asm("rcp.approx.f32 %0, %1;" : "=f"(r0) : "f"(e0 + 1.0f));
        asm("rcp.approx.f32 %0, %1;" : "=f"(r1) : "f"(e1 + 1.0f));
        asm("rcp.approx.f32 %0, %1;" : "=f"(r2) : "f"(e2 + 1.0f));
        asm("rcp.approx.f32 %0, %1;" : "=f"(r3) : "f"(e3 + 1.0f));
        sc0 = fmaf(v2.x, r0, sc0);
        sc0 = fmaf(v2.y, r1, sc0);
        sc1 = fmaf(v2.x, r2, sc1);
        sc1 = fmaf(v2.y, r3, sc1);
    }

    // reduce over the 4 lanes sharing a t-row
    sc0 += __shfl_xor_sync(0xffffffffu, sc0, 1);
    sc0 += __shfl_xor_sync(0xffffffffu, sc0, 2);
    sc1 += __shfl_xor_sync(0xffffffffu, sc1, 1);
    sc1 += __shfl_xor_sync(0xffffffffu, sc1, 2);
    if (tg == 0) {
        const int isf = g_det[1], isu8 = g_det[0];
        const float base = sh_V + vb0;
        const int t = t0 + w * 16 + g;
        float s0 = sc0 + base;
        float s1 = sc1 + base;
        if (mask_at(mask, b * T_ + t, isf, isu8))     s0 = NEG_;
        if (mask_at(mask, b * T_ + t + 8, isf, isu8)) s1 = NEG_;
        g_S[b * T_ + t]     = s0;
        g_S[b * T_ + t + 8] = s1;
    }
}

// ---------------- K4: softmax per row ----------------
__global__ void k_softmax(float* __restrict__ align_out) {
    const int b = blockIdx.x, tid = threadIdx.x;   // 512 threads
    __shared__ float sha[16], shb[16];
    float v[8];
    float mx = -3.4e38f;
#pragma unroll
    for (int i = 0; i < 8; ++i) {
        v[i] = g_S[b * T_ + tid + i * 512];
        mx = fmaxf(mx, v[i]);
    }
#pragma unroll
    for (int o = 16; o > 0; o >>= 1) mx = fmaxf(mx, __shfl_xor_sync(0xffffffffu, mx, o));
    if ((tid & 31) == 0) sha[tid >> 5] = mx;
    __syncthreads();
    if (tid < 32) {
        float t = (tid < 16) ? sha[tid] : -3.4e38f;
#pragma unroll
        for (int o = 8; o > 0; o >>= 1) t = fmaxf(t, __shfl_xor_sync(0xffffffffu, t, o));
        if (tid == 0) sha[0] = t;
    }
    __syncthreads();
    mx = sha[0];
    float sum = 0.0f;
#pragma unroll
    for (int i = 0; i < 8; ++i) { v[i] = __expf(v[i] - mx); sum += v[i]; }
#pragma unroll
    for (int o = 16; o > 0; o >>= 1) sum += __shfl_xor_sync(0xffffffffu, sum, o);
    if ((tid & 31) == 0) shb[tid >> 5] = sum;
    __syncthreads();
    if (tid < 32) {
        float t = (tid < 16) ? shb[tid] : 0.0f;
#pragma unroll
        for (int o = 8; o > 0; o >>= 1) t += __shfl_xor_sync(0xffffffffu, t, o);
        if (tid == 0) shb[0] = t;
    }
    __syncthreads();
    const float inv = 1.0f / shb[0];
#pragma unroll
    for (int i = 0; i < 8; ++i)
        align_out[b * T_ + tid + i * 512] = v[i] * inv;
}

// ---------------- K5: context partials (16 splits) + K6: reduce ----------------
__global__ void __launch_bounds__(256) k_context(const float* __restrict__ values,
                                                 const float* __restrict__ align) {
    __shared__ float al[256];
    const int b = blockIdx.y, sp = blockIdx.x, tid = threadIdx.x;
    const int tbase = sp * 256;
    al[tid] = align[b * T_ + tbase + tid];
    __syncthreads();
    const float* vp = values + ((size_t)(b * T_ + tbase)) * DIM_ + tid;
    float acc = 0.0f;
#pragma unroll 16
    for (int t = 0; t < 256; ++t)
        acc = fmaf(al[t], vp[(size_t)t * DIM_], acc);
    g_partial[(sp * B_ + b) * DIM_ + tid] = acc;
}

__global__ void k_reduce(float* __restrict__ att_out) {
    const int b = blockIdx.x, d = threadIdx.x;
    float s = 0.0f;
#pragma unroll
    for (int sp = 0; sp < NSPLIT; ++sp) s += g_partial[(sp * B_ + b) * DIM_ + d];
    att_out[b * DIM_ + d] = s;
}

// ---------------- launch ----------------
extern "C" void kernel_launch(void* const* d_in, const int* in_sizes, int n_in,
                              void* d_out, int out_size) {
    const float* query  = (const float*)d_in[0];
    const float* keys   = (const float*)d_in[1];
    const float* values = (const float*)d_in[2];
    const float* pa     = (const float*)d_in[3];
    const void*  mask   = d_in[4];
    const float* Wq     = (const float*)d_in[5];
    const float* cw     = (const float*)d_in[6];
    const float* Wloc   = (const float*)d_in[7];
    const float* vw     = (const float*)d_in[8];
    const float* vb     = (const float*)d_in[9];

    float* out = (float*)d_out;
    float *att_ptr, *align_ptr;
    if (out_size >= B_ * DIM_ + BT_) {
        att_ptr = out;
        align_ptr = out + B_ * DIM_;
    } else if (out_size == BT_) {
        float* p; cudaGetSymbolAddress((void**)&p, g_att_scratch);
        att_ptr = p; align_ptr = out;
    } else {
        float* p; cudaGetSymbolAddress((void**)&p, g_align_scratch);
        att_ptr = out; align_ptr = p;
    }

    k_reset<<<1, 1>>>();
    k_detect<<<64, 256>>>((const unsigned int*)mask);
    k_qproj<<<dim3(2, B_), 256>>>(query, Wq);
    k_score<<<dim3(T_ / 128, B_), 256>>>(keys, Wloc, vw, vb, mask, pa, cw);
    k_softmax<<<B_, 512>>>(align_ptr);
    k_context<<<dim3(NSPLIT, B_), 256>>>(values, align_ptr);
    k_reduce<<<B_, DIM_>>>(att_ptr);
}

// round 16
// speedup vs baseline: 1.1224x; 1.1224x over previous
#include <cuda_runtime.h>
#include <cuda_bf16.h>
#include <cstdint>

#define B_   64
#define T_   4096
#define DIM_ 256
#define NF_  32
#define KS_  31
#define PAD_ 15
#define NEG_ (-1e30f)
#define BT_  (B_ * T_)
#define NSPLIT 16
#define CE    2.885390081777926815f   // 2*log2(e)

// ---------------- scratch (device globals; no allocations) ----------------
__device__ float g_q[B_ * DIM_];                     // 64 KB
__device__ float g_S[BT_];                           // raw masked scores
__device__ float g_partial[NSPLIT * B_ * DIM_];      // context partials
__device__ float g_align_scratch[BT_];
__device__ float g_att_scratch[B_ * DIM_];
__device__ int   g_det[2];

// ---------------- K0: mask dtype detection ----------------
__global__ void k_reset() { g_det[0] = 0; g_det[1] = 0; }

// sample first 65536 words (256KB == min possible mask buffer size)
__global__ void k_detect(const unsigned int* __restrict__ mw) {
    int i = (blockIdx.x * 256 + threadIdx.x) * 4;
#pragma unroll
    for (int j = 0; j < 4; ++j) {
        unsigned v = mw[i + j];
        if (v == 0x3f800000u)      atomicOr(&g_det[1], 1);   // float 1.0
        else if (v > 1u)           atomicOr(&g_det[0], 1);   // packed bytes
    }
}

__device__ __forceinline__ bool mask_at(const void* m, int idx, int isf, int isu8) {
    if (isf)  return ((const float*)m)[idx] != 0.0f;
    if (isu8) return ((const unsigned char*)m)[idx] != 0;
    return ((const int*)m)[idx] != 0;
}

__device__ __forceinline__ uint32_t pkbf(float lo, float hi) {
    unsigned a = __bfloat16_as_ushort(__float2bfloat16(lo));
    unsigned b = __bfloat16_as_ushort(__float2bfloat16(hi));
    return a | (b << 16);
}

// ---------------- K1: q = query @ Wq^T  (4-way interleaved, 128 blocks) ---
__global__ void __launch_bounds__(256) k_qproj(const float* __restrict__ query,
                                               const float* __restrict__ Wq) {
    __shared__ float qs[DIM_];
    const int b = blockIdx.y, half = blockIdx.x;
    const int tid = threadIdx.x, w = tid >> 5, lane = tid & 31;
    qs[tid] = query[b * DIM_ + tid];
    __syncthreads();
    const int dbase = half * 128 + w * 16;
#pragma unroll
    for (int it = 0; it < 4; ++it) {
        const int d0 = dbase + it * 4;
        float a0 = 0.f, a1 = 0.f, a2 = 0.f, a3 = 0.f;
        const float* r0 = Wq + (size_t)(d0 + 0) * DIM_;
        const float* r1 = Wq + (size_t)(d0 + 1) * DIM_;
        const float* r2 = Wq + (size_t)(d0 + 2) * DIM_;
        const float* r3 = Wq + (size_t)(d0 + 3) * DIM_;
#pragma unroll
        for (int e = 0; e < 8; ++e) {
            const int c = lane + 32 * e;
            const float q = qs[c];
            a0 = fmaf(r0[c], q, a0);
            a1 = fmaf(r1[c], q, a1);
            a2 = fmaf(r2[c], q, a2);
            a3 = fmaf(r3[c], q, a3);
        }
#pragma unroll
        for (int o = 16; o > 0; o >>= 1) {
            a0 += __shfl_xor_sync(0xffffffffu, a0, o);
            a1 += __shfl_xor_sync(0xffffffffu, a1, o);
            a2 += __shfl_xor_sync(0xffffffffu, a2, o);
            a3 += __shfl_xor_sync(0xffffffffu, a3, o);
        }
        if (lane == 0)
            *(float4*)&g_q[b * DIM_ + d0] = make_float4(a0, a1, a2, a3);
    }
}

// ---------------- K3: fused conv + score kernel ----------------
#define FP 40   // bf16 smem pitch for F tile

__global__ void __launch_bounds__(256, 4)
k_score(const float* __restrict__ keys, const float* __restrict__ Wloc,
        const float* __restrict__ vw, const float* __restrict__ vb,
        const void* __restrict__ mask,
        const float* __restrict__ pa, const float* __restrict__ cw) {
    __shared__ __align__(16) uint4 Wfrag[32 * 32];            // 16 KB fragment quads
    __shared__ __align__(16) __nv_bfloat16 F_sh[128 * FP];    // 10 KB
    __shared__ __align__(16) float4 qv_sh[128];               // 2 KB {qC0,qC1,vm0,vm1}
    __shared__ float pa_sh[160];
    __shared__ float cw_sh[NF_ * KS_];
    __shared__ float sh_V;                                    // sum of v_w

    const int b = blockIdx.y, t0 = blockIdx.x * 128;
    const int tid = threadIdx.x, w = tid >> 5, lane = tid & 31;
    const int g = lane >> 2, tg = lane & 3;

    // ---- stage Wfrag: per (nt,lane) B-fragment quad, bf16-packed ----
    for (int idx = tid; idx < 1024; idx += 256) {
        const int ln = idx & 31;
        const int dd = (idx >> 5) * 8 + (ln >> 2);
        const float* Wr = Wloc + dd * NF_ + 2 * (ln & 3);
        uint4 wq;
        wq.x = pkbf(Wr[0],  Wr[1]);
        wq.y = pkbf(Wr[8],  Wr[9]);
        wq.z = pkbf(Wr[16], Wr[17]);
        wq.w = pkbf(Wr[24], Wr[25]);
        Wfrag[idx] = wq;
    }
    // ---- stage qv: {q*CE, q*CE, -2v, -2v} per d-pair ----
    if (tid < 128) {
        const float q0 = g_q[b * DIM_ + 2 * tid]     * CE;
        const float q1 = g_q[b * DIM_ + 2 * tid + 1] * CE;
        const float v0 = vw[2 * tid], v1 = vw[2 * tid + 1];
        qv_sh[tid] = make_float4(q0, q1, -2.0f * v0, -2.0f * v1);
    }
    // ---- V = sum(v_w) (warp 0, from global; safely before the sync) ----
    if (w == 0) {
        float s = 0.0f;
#pragma unroll
        for (int e = 0; e < 8; ++e) s += __ldg(&vw[lane + 32 * e]);
#pragma unroll
        for (int o = 16; o > 0; o >>= 1) s += __shfl_xor_sync(0xffffffffu, s, o);
        if (lane == 0) sh_V = s;
    }
    for (int i = tid; i < 160; i += 256) {
        int t = t0 + i - PAD_;
        pa_sh[i] = (t >= 0 && t < T_) ? pa[b * T_ + t] : 0.0f;
    }
    for (int i = tid; i < NF_ * KS_; i += 256) cw_sh[i] = cw[i];
    const float vb0 = vb[0];
    __syncthreads();

    // ---- conv for this warp's 16 t-rows (lane = filter), k-outer, low regs ----
    {
        float out[16], pv[16];
#pragma unroll
        for (int i = 0; i < 16; ++i) out[i] = 0.0f;
#pragma unroll
        for (int j = 0; j < 16; ++j) pv[j] = pa_sh[w * 16 + j];
#pragma unroll
        for (int k = 0; k < KS_; ++k) {
            const float cv = cw_sh[lane * KS_ + k];   // stride-31: conflict-free
#pragma unroll
            for (int i = 0; i < 16; ++i) out[i] = fmaf(pv[i], cv, out[i]);
            if (k < KS_ - 1) {
#pragma unroll
                for (int j = 0; j < 15; ++j) pv[j] = pv[j + 1];
                pv[15] = pa_sh[w * 16 + k + 16];      // max idx 157 < 160
            }
        }
        uint32_t* Frow = (uint32_t*)(F_sh + (w * 16) * FP);
#pragma unroll
        for (int i = 0; i < 16; ++i) {
            unsigned us = __bfloat16_as_ushort(__float2bfloat16(out[i]));
            unsigned nxt = __shfl_down_sync(0xffffffffu, us, 1);
            if (!(lane & 1))
                Frow[i * (FP / 2) + (lane >> 1)] = us | (nxt << 16);
        }
    }
    __syncwarp();   // F rows produced and consumed by the same warp

    // ---- A fragments (m16k16, 2 k-steps) ----
    const __nv_bfloat16* Fb = F_sh + (w * 16) * FP;
    uint32_t a[2][4];
#pragma unroll
    for (int ks = 0; ks < 2; ++ks) {
        const int f0 = ks * 16 + 2 * tg;
        a[ks][0] = *(const uint32_t*)(Fb + g * FP + f0);
        a[ks][1] = *(const uint32_t*)(Fb + (g + 8) * FP + f0);
        a[ks][2] = *(const uint32_t*)(Fb + g * FP + f0 + 8);
        a[ks][3] = *(const uint32_t*)(Fb + (g + 8) * FP + f0 + 8);
    }

    const size_t row0 = (size_t)(b * T_ + t0 + w * 16 + g) * DIM_;
    const float2* kp0 = (const float2*)(keys + row0) + tg;
    const float2* kp8 = (const float2*)(keys + row0 + 8 * DIM_) + tg;
    const uint4* Wp = Wfrag + lane;
    float sc0 = 0.0f, sc1 = 0.0f;

#pragma unroll 2
    for (int nt = 0; nt < 32; ++nt) {
        const uint4 wq = Wp[nt * 32];                  // one LDS.128
        const float2 k0 = __ldcs(kp0); kp0 += 4;       // streaming keys
        const float2 k1 = __ldcs(kp8); kp8 += 4;
        const float4 qv = qv_sh[nt * 4 + tg];          // one LDS.128 (broadcast x4)

        float c0 = 0.f, c1 = 0.f, c2 = 0.f, c3 = 0.f;
        asm volatile(
            "mma.sync.aligned.m16n8k16.row.col.f32.bf16.bf16.f32 "
            "{%0,%1,%2,%3}, {%4,%5,%6,%7}, {%8,%9}, {%0,%1,%2,%3};"
            : "+f"(c0), "+f"(c1), "+f"(c2), "+f"(c3)
            : "r"(a[0][0]), "r"(a[0][1]), "r"(a[0][2]), "r"(a[0][3]),
              "r"(wq.x), "r"(wq.y));
        asm volatile(
            "mma.sync.aligned.m16n8k16.row.col.f32.bf16.bf16.f32 "
            "{%0,%1,%2,%3}, {%4,%5,%6,%7}, {%8,%9}, {%0,%1,%2,%3};"
            : "+f"(c0), "+f"(c1), "+f"(c2), "+f"(c3)
            : "r"(a[1][0]), "r"(a[1][1]), "r"(a[1][2]), "r"(a[1][3]),
              "r"(wq.z), "r"(wq.w));

        // v*tanh(x) = v - 2v*rcp(ex2(x*CE)+1);  qv.z/.w = -2v, V added at end
        const float kC0x = fmaf(k0.x, CE, qv.x);
        const float kC0y = fmaf(k0.y, CE, qv.y);
        const float kC1x = fmaf(k1.x, CE, qv.x);
        const float kC1y = fmaf(k1.y, CE, qv.y);
        float e0, e1, e2, e3;
        asm("ex2.approx.f32 %0, %1;" : "=f"(e0) : "f"(fmaf(c0, CE, kC0x)));
        asm("ex2.approx.f32 %0, %1;" : "=f"(e1) : "f"(fmaf(c1, CE, kC0y)));
        asm("ex2.approx.f32 %0, %1;" : "=f"(e2) : "f"(fmaf(c2, CE, kC1x)));
        asm("ex2.approx.f32 %0, %1;" : "=f"(e3) : "f"(fmaf(c3, CE, kC1y)));
        asm("rcp.approx.f32 %0, %1;" : "=f"(e0) : "f"(e0 + 1.0f));
        asm("rcp.approx.f32 %0, %1;" : "=f"(e1) : "f"(e1 + 1.0f));
        asm("rcp.approx.f32 %0, %1;" : "=f"(e2) : "f"(e2 + 1.0f));
        asm("rcp.approx.f32 %0, %1;" : "=f"(e3) : "f"(e3 + 1.0f));
        sc0 = fmaf(qv.z, e0, sc0);
        sc0 = fmaf(qv.w, e1, sc0);
        sc1 = fmaf(qv.z, e2, sc1);
        sc1 = fmaf(qv.w, e3, sc1);
    }

    // reduce over the 4 lanes sharing a t-row
    sc0 += __shfl_xor_sync(0xffffffffu, sc0, 1);
    sc0 += __shfl_xor_sync(0xffffffffu, sc0, 2);
    sc1 += __shfl_xor_sync(0xffffffffu, sc1, 1);
    sc1 += __shfl_xor_sync(0xffffffffu, sc1, 2);
    if (tg == 0) {
        const int isf = g_det[1], isu8 = g_det[0];
        const float base = sh_V + vb0;
        const int t = t0 + w * 16 + g;
        float s0 = sc0 + base;
        float s1 = sc1 + base;
        if (mask_at(mask, b * T_ + t, isf, isu8))     s0 = NEG_;
        if (mask_at(mask, b * T_ + t + 8, isf, isu8)) s1 = NEG_;
        g_S[b * T_ + t]     = s0;
        g_S[b * T_ + t + 8] = s1;
    }
}

// ---------------- K4: softmax per row ----------------
__global__ void k_softmax(float* __restrict__ align_out) {
    const int b = blockIdx.x, tid = threadIdx.x;   // 512 threads
    __shared__ float sha[16], shb[16];
    float v[8];
    float mx = -3.4e38f;
#pragma unroll
    for (int i = 0; i < 8; ++i) {
        v[i] = g_S[b * T_ + tid + i * 512];
        mx = fmaxf(mx, v[i]);
    }
#pragma unroll
    for (int o = 16; o > 0; o >>= 1) mx = fmaxf(mx, __shfl_xor_sync(0xffffffffu, mx, o));
    if ((tid & 31) == 0) sha[tid >> 5] = mx;
    __syncthreads();
    if (tid < 32) {
        float t = (tid < 16) ? sha[tid] : -3.4e38f;
#pragma unroll
        for (int o = 8; o > 0; o >>= 1) t = fmaxf(t, __shfl_xor_sync(0xffffffffu, t, o));
        if (tid == 0) sha[0] = t;
    }
    __syncthreads();
    mx = sha[0];
    float sum = 0.0f;
#pragma unroll
    for (int i = 0; i < 8; ++i) { v[i] = __expf(v[i] - mx); sum += v[i]; }
#pragma unroll
    for (int o = 16; o > 0; o >>= 1) sum += __shfl_xor_sync(0xffffffffu, sum, o);
    if ((tid & 31) == 0) shb[tid >> 5] = sum;
    __syncthreads();
    if (tid < 32) {
        float t = (tid < 16) ? shb[tid] : 0.0f;
#pragma unroll
        for (int o = 8; o > 0; o >>= 1) t += __shfl_xor_sync(0xffffffffu, t, o);
        if (tid == 0) shb[0] = t;
    }
    __syncthreads();
    const float inv = 1.0f / shb[0];
#pragma unroll
    for (int i = 0; i < 8; ++i)
        align_out[b * T_ + tid + i * 512] = v[i] * inv;
}

// ---------------- K5: context partials (float4) + K6: reduce ----------------
__global__ void __launch_bounds__(256) k_context(const float* __restrict__ values,
                                                 const float* __restrict__ align) {
    __shared__ float al[256];
    __shared__ float4 red[256];
    const int b = blockIdx.y, sp = blockIdx.x, tid = threadIdx.x;
    const int tbase = sp * 256;
    al[tid] = align[b * T_ + tbase + tid];
    __syncthreads();
    const int d4 = (tid & 63) * 4;     // 4 contiguous d per thread
    const int tro = tid >> 6;          // 4 t-rows in flight
    const float4* vp = (const float4*)(values + ((size_t)(b * T_ + tbase + tro)) * DIM_ + d4);
    float4 acc = make_float4(0.f, 0.f, 0.f, 0.f);
#pragma unroll 8
    for (int t = 0; t < 256; t += 4) {
        const float a = al[t + tro];
        const float4 v4 = __ldcs(vp);
        vp += DIM_;                    // 4 rows of 256 floats = 256 float4
        acc.x = fmaf(a, v4.x, acc.x);
        acc.y = fmaf(a, v4.y, acc.y);
        acc.z = fmaf(a, v4.z, acc.z);
        acc.w = fmaf(a, v4.w, acc.w);
    }
    red[tid] = acc;
    __syncthreads();
    if (tid < 64) {
        float4 r0 = red[tid], r1 = red[tid + 64], r2 = red[tid + 128], r3 = red[tid + 192];
        r0.x += r1.x + r2.x + r3.x;
        r0.y += r1.y + r2.y + r3.y;
        r0.z += r1.z + r2.z + r3.z;
        r0.w += r1.w + r2.w + r3.w;
        *(float4*)&g_partial[(sp * B_ + b) * DIM_ + tid * 4] = r0;
    }
}

__global__ void k_reduce(float* __restrict__ att_out) {
    const int b = blockIdx.x, d = threadIdx.x;
    float s = 0.0f;
#pragma unroll
    for (int sp = 0; sp < NSPLIT; ++sp) s += g_partial[(sp * B_ + b) * DIM_ + d];
    att_out[b * DIM_ + d] = s;
}

// ---------------- launch ----------------
extern "C" void kernel_launch(void* const* d_in, const int* in_sizes, int n_in,
                              void* d_out, int out_size) {
    const float* query  = (const float*)d_in[0];
    const float* keys   = (const float*)d_in[1];
    const float* values = (const float*)d_in[2];
    const float* pa     = (const float*)d_in[3];
    const void*  mask   = d_in[4];
    const float* Wq     = (const float*)d_in[5];
    const float* cw     = (const float*)d_in[6];
    const float* Wloc   = (const float*)d_in[7];
    const float* vw     = (const float*)d_in[8];
    const float* vb     = (const float*)d_in[9];

    float* out = (float*)d_out;
    float *att_ptr, *align_ptr;
    if (out_size >= B_ * DIM_ + BT_) {
        att_ptr = out;
        align_ptr = out + B_ * DIM_;
    } else if (out_size == BT_) {
        float* p; cudaGetSymbolAddress((void**)&p, g_att_scratch);
        att_ptr = p; align_ptr = out;
    } else {
        float* p; cudaGetSymbolAddress((void**)&p, g_align_scratch);
        att_ptr = out; align_ptr = p;
    }

    k_reset<<<1, 1>>>();
    k_detect<<<64, 256>>>((const unsigned int*)mask);
    k_qproj<<<dim3(2, B_), 256>>>(query, Wq);
    k_score<<<dim3(T_ / 128, B_), 256>>>(keys, Wloc, vw, vb, mask, pa, cw);
    k_softmax<<<B_, 512>>>(align_ptr);
    k_context<<<dim3(NSPLIT, B_), 256>>>(values, align_ptr);
    k_reduce<<<B_, DIM_>>>(att_ptr);
}

// round 17
// speedup vs baseline: 1.2467x; 1.1107x over previous
#include <cuda_runtime.h>
#include <cuda_bf16.h>
#include <cstdint>

#define B_   64
#define T_   4096
#define DIM_ 256
#define NF_  32
#define KS_  31
#define PAD_ 15
#define NEG_ (-1e30f)
#define BT_  (B_ * T_)
#define NBLK 32                        // t-splits per batch
#define CE    2.885390081777926815f    // 2*log2(e)
#define L2E   1.4426950408889634074f   // log2(e)

// ---------------- scratch (device globals; no allocations) ----------------
__device__ float g_q[B_ * DIM_];                    // 64 KB
__device__ float g_S[BT_];                          // raw masked scores
__device__ float g_ctx[(size_t)B_ * NBLK * DIM_];   // 2 MB partial contexts
__device__ float g_ml[B_ * NBLK * 2];               // per-partial (m, l)
__device__ float g_bm[B_], g_bil[B_];               // per-batch (m_g, 1/l_g)
__device__ float g_align_scratch[BT_];
__device__ float g_att_scratch[B_ * DIM_];
__device__ int   g_det[2];

// ---------------- K0: mask dtype detection ----------------
__global__ void k_reset() { g_det[0] = 0; g_det[1] = 0; }

// sample first 65536 words (256KB == min possible mask buffer size)
__global__ void k_detect(const unsigned int* __restrict__ mw) {
    int i = (blockIdx.x * 256 + threadIdx.x) * 4;
#pragma unroll
    for (int j = 0; j < 4; ++j) {
        unsigned v = mw[i + j];
        if (v == 0x3f800000u)      atomicOr(&g_det[1], 1);   // float 1.0
        else if (v > 1u)           atomicOr(&g_det[0], 1);   // packed bytes
    }
}

__device__ __forceinline__ bool mask_at(const void* m, int idx, int isf, int isu8) {
    if (isf)  return ((const float*)m)[idx] != 0.0f;
    if (isu8) return ((const unsigned char*)m)[idx] != 0;
    return ((const int*)m)[idx] != 0;
}

__device__ __forceinline__ uint32_t pkbf(float lo, float hi) {
    unsigned a = __bfloat16_as_ushort(__float2bfloat16(lo));
    unsigned b = __bfloat16_as_ushort(__float2bfloat16(hi));
    return a | (b << 16);
}

// ---------------- K1: q = query @ Wq^T ----------------
__global__ void __launch_bounds__(256) k_qproj(const float* __restrict__ query,
                                               const float* __restrict__ Wq) {
    __shared__ float qs[DIM_];
    const int b = blockIdx.y, half = blockIdx.x;
    const int tid = threadIdx.x, w = tid >> 5, lane = tid & 31;
    qs[tid] = query[b * DIM_ + tid];
    __syncthreads();
    const int dbase = half * 128 + w * 16;
#pragma unroll
    for (int it = 0; it < 4; ++it) {
        const int d0 = dbase + it * 4;
        float a0 = 0.f, a1 = 0.f, a2 = 0.f, a3 = 0.f;
        const float* r0 = Wq + (size_t)(d0 + 0) * DIM_;
        const float* r1 = Wq + (size_t)(d0 + 1) * DIM_;
        const float* r2 = Wq + (size_t)(d0 + 2) * DIM_;
        const float* r3 = Wq + (size_t)(d0 + 3) * DIM_;
#pragma unroll
        for (int e = 0; e < 8; ++e) {
            const int c = lane + 32 * e;
            const float q = qs[c];
            a0 = fmaf(r0[c], q, a0);
            a1 = fmaf(r1[c], q, a1);
            a2 = fmaf(r2[c], q, a2);
            a3 = fmaf(r3[c], q, a3);
        }
#pragma unroll
        for (int o = 16; o > 0; o >>= 1) {
            a0 += __shfl_xor_sync(0xffffffffu, a0, o);
            a1 += __shfl_xor_sync(0xffffffffu, a1, o);
            a2 += __shfl_xor_sync(0xffffffffu, a2, o);
            a3 += __shfl_xor_sync(0xffffffffu, a3, o);
        }
        if (lane == 0)
            *(float4*)&g_q[b * DIM_ + d0] = make_float4(a0, a1, a2, a3);
    }
}

// ---------------- K3: fused conv + score + partial softmax-context --------
#define FP 40   // bf16 smem pitch for F tile

__global__ void __launch_bounds__(256, 4)
k_fused(const float* __restrict__ keys, const float* __restrict__ values,
        const float* __restrict__ Wloc,
        const float* __restrict__ vw, const float* __restrict__ vb,
        const void* __restrict__ mask,
        const float* __restrict__ pa, const float* __restrict__ cw) {
    __shared__ __align__(16) uint4 Wfrag[32 * 32];            // 16 KB fragment quads
    __shared__ __align__(16) __nv_bfloat16 F_sh[128 * FP];    // 10 KB
    __shared__ __align__(16) float4 qv_sh[128];               // 2 KB {qC0,qC1,vm0,vm1}
    __shared__ __align__(16) float4 acc_sh[512];              // 8 KB warp partial acc
    __shared__ float pa_sh[160];
    __shared__ float cw_sh[NF_ * KS_];
    __shared__ float sc_sh[128];                              // block raw scores
    __shared__ float l_sh[8];
    __shared__ float sh_V, sh_mB;

    const int b = blockIdx.y, t0 = blockIdx.x * 128;
    const int tid = threadIdx.x, w = tid >> 5, lane = tid & 31;
    const int g = lane >> 2, tg = lane & 3;

    // ---- stage Wfrag: per (nt,lane) B-fragment quad, bf16-packed ----
    for (int idx = tid; idx < 1024; idx += 256) {
        const int ln = idx & 31;
        const int dd = (idx >> 5) * 8 + (ln >> 2);
        const float* Wr = Wloc + dd * NF_ + 2 * (ln & 3);
        uint4 wq;
        wq.x = pkbf(Wr[0],  Wr[1]);
        wq.y = pkbf(Wr[8],  Wr[9]);
        wq.z = pkbf(Wr[16], Wr[17]);
        wq.w = pkbf(Wr[24], Wr[25]);
        Wfrag[idx] = wq;
    }
    // ---- stage qv: {q*CE, q*CE, -2v, -2v} per d-pair ----
    if (tid < 128) {
        const float q0 = g_q[b * DIM_ + 2 * tid]     * CE;
        const float q1 = g_q[b * DIM_ + 2 * tid + 1] * CE;
        const float v0 = vw[2 * tid], v1 = vw[2 * tid + 1];
        qv_sh[tid] = make_float4(q0, q1, -2.0f * v0, -2.0f * v1);
    }
    // ---- V = sum(v_w) (warp 0, from global; safely before the sync) ----
    if (w == 0) {
        float s = 0.0f;
#pragma unroll
        for (int e = 0; e < 8; ++e) s += __ldg(&vw[lane + 32 * e]);
#pragma unroll
        for (int o = 16; o > 0; o >>= 1) s += __shfl_xor_sync(0xffffffffu, s, o);
        if (lane == 0) sh_V = s;
    }
    for (int i = tid; i < 160; i += 256) {
        int t = t0 + i - PAD_;
        pa_sh[i] = (t >= 0 && t < T_) ? pa[b * T_ + t] : 0.0f;
    }
    for (int i = tid; i < NF_ * KS_; i += 256) cw_sh[i] = cw[i];
    const float vb0 = vb[0];
    __syncthreads();

    // ---- conv for this warp's 16 t-rows (lane = filter) ----
    {
        float out[16], pv[16];
#pragma unroll
        for (int i = 0; i < 16; ++i) out[i] = 0.0f;
#pragma unroll
        for (int j = 0; j < 16; ++j) pv[j] = pa_sh[w * 16 + j];
#pragma unroll
        for (int k = 0; k < KS_; ++k) {
            const float cv = cw_sh[lane * KS_ + k];   // stride-31: conflict-free
#pragma unroll
            for (int i = 0; i < 16; ++i) out[i] = fmaf(pv[i], cv, out[i]);
            if (k < KS_ - 1) {
#pragma unroll
                for (int j = 0; j < 15; ++j) pv[j] = pv[j + 1];
                pv[15] = pa_sh[w * 16 + k + 16];      // max idx 157 < 160
            }
        }
        uint32_t* Frow = (uint32_t*)(F_sh + (w * 16) * FP);
#pragma unroll
        for (int i = 0; i < 16; ++i) {
            unsigned us = __bfloat16_as_ushort(__float2bfloat16(out[i]));
            unsigned nxt = __shfl_down_sync(0xffffffffu, us, 1);
            if (!(lane & 1))
                Frow[i * (FP / 2) + (lane >> 1)] = us | (nxt << 16);
        }
    }
    __syncwarp();   // F rows produced and consumed by the same warp

    // ---- A fragments (m16k16, 2 k-steps) ----
    const __nv_bfloat16* Fb = F_sh + (w * 16) * FP;
    uint32_t a[2][4];
#pragma unroll
    for (int ks = 0; ks < 2; ++ks) {
        const int f0 = ks * 16 + 2 * tg;
        a[ks][0] = *(const uint32_t*)(Fb + g * FP + f0);
        a[ks][1] = *(const uint32_t*)(Fb + (g + 8) * FP + f0);
        a[ks][2] = *(const uint32_t*)(Fb + g * FP + f0 + 8);
        a[ks][3] = *(const uint32_t*)(Fb + (g + 8) * FP + f0 + 8);
    }

    const size_t row0 = (size_t)(b * T_ + t0 + w * 16 + g) * DIM_;
    const float2* kp0 = (const float2*)(keys + row0) + tg;
    const float2* kp8 = (const float2*)(keys + row0 + 8 * DIM_) + tg;
    const uint4* Wp = Wfrag + lane;
    float sc0 = 0.0f, sc1 = 0.0f;

#pragma unroll 2
    for (int nt = 0; nt < 32; ++nt) {
        const uint4 wq = Wp[nt * 32];                  // one LDS.128
        const float2 k0 = __ldcs(kp0); kp0 += 4;       // streaming keys
        const float2 k1 = __ldcs(kp8); kp8 += 4;
        const float4 qv = qv_sh[nt * 4 + tg];          // one LDS.128 (broadcast x4)

        float c0 = 0.f, c1 = 0.f, c2 = 0.f, c3 = 0.f;
        asm volatile(
            "mma.sync.aligned.m16n8k16.row.col.f32.bf16.bf16.f32 "
            "{%0,%1,%2,%3}, {%4,%5,%6,%7}, {%8,%9}, {%0,%1,%2,%3};"
            : "+f"(c0), "+f"(c1), "+f"(c2), "+f"(c3)
            : "r"(a[0][0]), "r"(a[0][1]), "r"(a[0][2]), "r"(a[0][3]),
              "r"(wq.x), "r"(wq.y));
        asm volatile(
            "mma.sync.aligned.m16n8k16.row.col.f32.bf16.bf16.f32 "
            "{%0,%1,%2,%3}, {%4,%5,%6,%7}, {%8,%9}, {%0,%1,%2,%3};"
            : "+f"(c0), "+f"(c1), "+f"(c2), "+f"(c3)
            : "r"(a[1][0]), "r"(a[1][1]), "r"(a[1][2]), "r"(a[1][3]),
              "r"(wq.z), "r"(wq.w));

        // v*tanh(x) = v - 2v*rcp(ex2(x*CE)+1);  qv.z/.w = -2v, V added at end
        const float kC0x = fmaf(k0.x, CE, qv.x);
        const float kC0y = fmaf(k0.y, CE, qv.y);
        const float kC1x = fmaf(k1.x, CE, qv.x);
        const float kC1y = fmaf(k1.y, CE, qv.y);
        float e0, e1, e2, e3;
        asm("ex2.approx.f32 %0, %1;" : "=f"(e0) : "f"(fmaf(c0, CE, kC0x)));
        asm("ex2.approx.f32 %0, %1;" : "=f"(e1) : "f"(fmaf(c1, CE, kC0y)));
        asm("ex2.approx.f32 %0, %1;" : "=f"(e2) : "f"(fmaf(c2, CE, kC1x)));
        asm("ex2.approx.f32 %0, %1;" : "=f"(e3) : "f"(fmaf(c3, CE, kC1y)));
        asm("rcp.approx.f32 %0, %1;" : "=f"(e0) : "f"(e0 + 1.0f));
        asm("rcp.approx.f32 %0, %1;" : "=f"(e1) : "f"(e1 + 1.0f));
        asm("rcp.approx.f32 %0, %1;" : "=f"(e2) : "f"(e2 + 1.0f));
        asm("rcp.approx.f32 %0, %1;" : "=f"(e3) : "f"(e3 + 1.0f));
        sc0 = fmaf(qv.z, e0, sc0);
        sc0 = fmaf(qv.w, e1, sc0);
        sc1 = fmaf(qv.z, e2, sc1);
        sc1 = fmaf(qv.w, e3, sc1);
    }

    // reduce over the 4 lanes sharing a t-row
    sc0 += __shfl_xor_sync(0xffffffffu, sc0, 1);
    sc0 += __shfl_xor_sync(0xffffffffu, sc0, 2);
    sc1 += __shfl_xor_sync(0xffffffffu, sc1, 1);
    sc1 += __shfl_xor_sync(0xffffffffu, sc1, 2);
    if (tg == 0) {
        const int isf = g_det[1], isu8 = g_det[0];
        const float base = sh_V + vb0;
        const int t = t0 + w * 16 + g;
        float s0 = sc0 + base;
        float s1 = sc1 + base;
        if (mask_at(mask, b * T_ + t, isf, isu8))     s0 = NEG_;
        if (mask_at(mask, b * T_ + t + 8, isf, isu8)) s1 = NEG_;
        g_S[b * T_ + t]     = s0;
        g_S[b * T_ + t + 8] = s1;
        sc_sh[w * 16 + g]     = s0;
        sc_sh[w * 16 + g + 8] = s1;
    }
    __syncthreads();

    // ---- phase 2: block max, exp weights, values accumulation ----
    if (w == 0) {
        float m = fmaxf(fmaxf(sc_sh[lane], sc_sh[lane + 32]),
                        fmaxf(sc_sh[lane + 64], sc_sh[lane + 96]));
#pragma unroll
        for (int o = 16; o > 0; o >>= 1)
            m = fmaxf(m, __shfl_xor_sync(0xffffffffu, m, o));
        if (lane == 0) sh_mB = m;
    }
    __syncthreads();
    const float mB = sh_mB;

    float4 a0 = make_float4(0.f, 0.f, 0.f, 0.f);
    float4 a1 = make_float4(0.f, 0.f, 0.f, 0.f);
    float lw = 0.0f;
    const float* vbase = values + (size_t)(b * T_ + t0 + w * 16) * DIM_;
#pragma unroll 4
    for (int i = 0; i < 16; ++i) {
        const float wgt = exp2f((sc_sh[w * 16 + i] - mB) * L2E);
        lw += wgt;
        const float4 v0 = __ldcs((const float4*)(vbase + (size_t)i * DIM_) + lane);
        const float4 v1 = __ldcs((const float4*)(vbase + (size_t)i * DIM_ + 128) + lane);
        a0.x = fmaf(wgt, v0.x, a0.x); a0.y = fmaf(wgt, v0.y, a0.y);
        a0.z = fmaf(wgt, v0.z, a0.z); a0.w = fmaf(wgt, v0.w, a0.w);
        a1.x = fmaf(wgt, v1.x, a1.x); a1.y = fmaf(wgt, v1.y, a1.y);
        a1.z = fmaf(wgt, v1.z, a1.z); a1.w = fmaf(wgt, v1.w, a1.w);
    }
    acc_sh[w * 64 + lane]      = a0;    // d = 4*lane
    acc_sh[w * 64 + 32 + lane] = a1;    // d = 128 + 4*lane
    if (lane == 0) l_sh[w] = lw;
    __syncthreads();

    const int pb = b * NBLK + blockIdx.x;
    if (tid < 64) {
        float4 s = acc_sh[tid];
#pragma unroll
        for (int ww = 1; ww < 8; ++ww) {
            const float4 r = acc_sh[ww * 64 + tid];
            s.x += r.x; s.y += r.y; s.z += r.z; s.w += r.w;
        }
        const int od = (tid & 31) * 4 + (tid >> 5) * 128;
        *(float4*)&g_ctx[(size_t)pb * DIM_ + od] = s;
    } else if (tid == 64) {
        float l = 0.0f;
#pragma unroll
        for (int ww = 0; ww < 8; ++ww) l += l_sh[ww];
        g_ml[pb * 2]     = mB;
        g_ml[pb * 2 + 1] = l;
    }
}

// ---------------- K4: finalize attention across partials ----------------
__global__ void k_finalize(float* __restrict__ att_out) {
    const int b = blockIdx.x, tid = threadIdx.x;
    __shared__ float r_sh[NBLK];
    __shared__ float sh_mg, sh_il;
    if (tid < 32) {
        const float mi = g_ml[(b * NBLK + tid) * 2];
        const float li = g_ml[(b * NBLK + tid) * 2 + 1];
        float mg = mi;
#pragma unroll
        for (int o = 16; o > 0; o >>= 1)
            mg = fmaxf(mg, __shfl_xor_sync(0xffffffffu, mg, o));
        const float r = exp2f((mi - mg) * L2E);
        r_sh[tid] = r;
        float ls = li * r;
#pragma unroll
        for (int o = 16; o > 0; o >>= 1) ls += __shfl_xor_sync(0xffffffffu, ls, o);
        if (tid == 0) {
            sh_mg = mg;
            sh_il = 1.0f / ls;
            g_bm[b] = mg;
            g_bil[b] = 1.0f / ls;
        }
    }
    __syncthreads();
    float s = 0.0f;
#pragma unroll 8
    for (int i = 0; i < NBLK; ++i)
        s = fmaf(g_ctx[(size_t)(b * NBLK + i) * DIM_ + tid], r_sh[i], s);
    att_out[b * DIM_ + tid] = s * sh_il;
}

// ---------------- K5: align = exp(S - m_g) / l_g ----------------
__global__ void k_align(float* __restrict__ align_out) {
    const int b = blockIdx.y;
    const int base = b * T_ + blockIdx.x * 1024 + threadIdx.x * 4;
    const float m = g_bm[b], il = g_bil[b];
    const float4 s4 = *(const float4*)&g_S[base];
    float4 o;
    o.x = exp2f((s4.x - m) * L2E) * il;
    o.y = exp2f((s4.y - m) * L2E) * il;
    o.z = exp2f((s4.z - m) * L2E) * il;
    o.w = exp2f((s4.w - m) * L2E) * il;
    *(float4*)&align_out[base] = o;
}

// ---------------- launch ----------------
extern "C" void kernel_launch(void* const* d_in, const int* in_sizes, int n_in,
                              void* d_out, int out_size) {
    const float* query  = (const float*)d_in[0];
    const float* keys   = (const float*)d_in[1];
    const float* values = (const float*)d_in[2];
    const float* pa     = (const float*)d_in[3];
    const void*  mask   = d_in[4];
    const float* Wq     = (const float*)d_in[5];
    const float* cw     = (const float*)d_in[6];
    const float* Wloc   = (const float*)d_in[7];
    const float* vw     = (const float*)d_in[8];
    const float* vb     = (const float*)d_in[9];

    float* out = (float*)d_out;
    float *att_ptr, *align_ptr;
    if (out_size >= B_ * DIM_ + BT_) {
        att_ptr = out;
        align_ptr = out + B_ * DIM_;
    } else if (out_size == BT_) {
        float* p; cudaGetSymbolAddress((void**)&p, g_att_scratch);
        att_ptr = p; align_ptr = out;
    } else {
        float* p; cudaGetSymbolAddress((void**)&p, g_align_scratch);
        att_ptr = out; align_ptr = p;
    }

    k_reset<<<1, 1>>>();
    k_detect<<<64, 256>>>((const unsigned int*)mask);
    k_qproj<<<dim3(2, B_), 256>>>(query, Wq);
    k_fused<<<dim3(NBLK, B_), 256>>>(keys, values, Wloc, vw, vb, mask, pa, cw);
    k_finalize<<<B_, 256>>>(att_ptr);
    k_align<<<dim3(4, B_), 256>>>(align_ptr);
}